// round 15
// baseline (speedup 1.0000x reference)
#include <cuda_runtime.h>
#include <cuda_fp16.h>
#include <math.h>
#include <stdint.h>

// ---------------- problem constants ----------------
#define BATCH 2
#define TT 8
#define HH 128
#define WWD 128
#define CC 192
#define TOKENS (BATCH*TT*HH*WWD)         // 262144
#define NWIN 2048
#define NWTOK 128
#define HEADS 6
#define HDIM 32
#define HIDDEN 768
#define QKVDIM 576
#define ATTSCALE 0.17677669529663687f

// ---------------- scratch ----------------
__device__ __half g_xw[(size_t)TOKENS * CC];
__device__ __half g_qkv[(size_t)NWIN * NWTOK * QKVDIM];
__device__ __half g_attnout[(size_t)TOKENS * CC];
__device__ float  g_x2[(size_t)TOKENS * CC];
__device__ __half g_h1[(size_t)TOKENS * HIDDEN];
__device__ __half g_wq[QKVDIM * CC];
__device__ __half g_wp[CC * CC];
__device__ __half g_w1[HIDDEN * CC];
__device__ __half g_w2[CC * HIDDEN];
__device__ float  g_biasf[HEADS * NWTOK * NWTOK];   // expanded rel-pos bias

// ---------------- helpers ----------------
__device__ __forceinline__ void cp_async16(uint32_t dst, const void* src) {
    asm volatile("cp.async.cg.shared.global [%0], [%1], 16;" :: "r"(dst), "l"(src));
}
__device__ __forceinline__ void cp_commit() { asm volatile("cp.async.commit_group;"); }
__device__ __forceinline__ void cp_wait1()  { asm volatile("cp.async.wait_group 1;"); }
__device__ __forceinline__ uint32_t smem_u32(const void* p) {
    uint32_t a;
    asm("{ .reg .u64 t; cvta.to.shared.u64 t, %1; cvt.u32.u64 %0, t; }" : "=r"(a) : "l"(p));
    return a;
}
__device__ __forceinline__ void mma_f16(float c[4], const uint32_t a[4], const uint32_t b[2]) {
    asm volatile(
        "mma.sync.aligned.m16n8k16.row.col.f32.f16.f16.f32 "
        "{%0,%1,%2,%3}, {%4,%5,%6,%7}, {%8,%9}, {%0,%1,%2,%3};"
        : "+f"(c[0]), "+f"(c[1]), "+f"(c[2]), "+f"(c[3])
        : "r"(a[0]), "r"(a[1]), "r"(a[2]), "r"(a[3]), "r"(b[0]), "r"(b[1]));
}
__device__ __forceinline__ void ldsm_x4(uint32_t r[4], uint32_t addr) {
    asm volatile("ldmatrix.sync.aligned.m8n8.x4.shared.b16 {%0,%1,%2,%3}, [%4];"
        : "=r"(r[0]), "=r"(r[1]), "=r"(r[2]), "=r"(r[3]) : "r"(addr));
}
__device__ __forceinline__ void stsm_x4(uint32_t addr, uint32_t r0, uint32_t r1,
                                        uint32_t r2, uint32_t r3) {
    asm volatile("stmatrix.sync.aligned.m8n8.x4.shared.b16 [%0], {%1,%2,%3,%4};"
        :: "r"(addr), "r"(r0), "r"(r1), "r"(r2), "r"(r3) : "memory");
}
__device__ __forceinline__ uint32_t pack2(float x, float y) {
    __half2 h = __floats2half2_rn(x, y);
    return *(uint32_t*)&h;
}
__device__ __forceinline__ float gelu_exact(float x) {
    return 0.5f * x * (1.0f + erff(x * 0.70710678118654752f));
}

// ---------------- LayerNorm -> half (window scatter), float2 I/O ------------
__global__ void ln_kernel(const float* __restrict__ in,
                          const float* __restrict__ g,
                          const float* __restrict__ b,
                          __half* __restrict__ out, int windowed)
{
    int token = (blockIdx.x << 3) + (threadIdx.x >> 5);
    int lane  = threadIdx.x & 31;
    size_t base = (size_t)token * CC;

    const float2* inp = (const float2*)(in + base);
    float2 v[3]; float s = 0.f;
    #pragma unroll
    for (int j = 0; j < 3; ++j) { v[j] = inp[lane + 32*j]; s += v[j].x + v[j].y; }
    #pragma unroll
    for (int o = 16; o; o >>= 1) s += __shfl_xor_sync(0xffffffffu, s, o);
    float mu = s * (1.0f/192.0f);
    float vs = 0.f;
    #pragma unroll
    for (int j = 0; j < 3; ++j) {
        float d0 = v[j].x - mu, d1 = v[j].y - mu;
        vs += d0*d0 + d1*d1;
    }
    #pragma unroll
    for (int o = 16; o; o >>= 1) vs += __shfl_xor_sync(0xffffffffu, vs, o);
    float rinv = rsqrtf(vs * (1.0f/192.0f) + 1e-5f);

    size_t obase;
    if (windowed) {
        int w = token & 127, h = (token >> 7) & 127, t = (token >> 14) & 7, bb = token >> 17;
        int win = ((bb*4 + (t >> 1))*16 + (h >> 3))*16 + (w >> 3);
        int n   = ((t & 1) << 6) | ((h & 7) << 3) | (w & 7);
        obase = ((size_t)win * NWTOK + n) * CC;
    } else obase = base;
    #pragma unroll
    for (int j = 0; j < 3; ++j) {
        int c = (lane + 32*j)*2;
        const float2 gg = *(const float2*)(g + c);
        const float2 bb = *(const float2*)(b + c);
        float n0 = (v[j].x - mu)*rinv*gg.x + bb.x;
        float n1 = (v[j].y - mu)*rinv*gg.y + bb.y;
        *(__half2*)(out + obase + c) = __floats2half2_rn(n0, n1);
    }
}

// ---------------- merged setup ----------------
#define NWQ (QKVDIM*CC)
#define NWP (CC*CC)
#define NW1 (HIDDEN*CC)
#define NW2 (CC*HIDDEN)
#define NBF (HEADS*NWTOK*NWTOK)
#define NSETUP (NWQ+NWP+NW1+NW2+NBF)

__global__ void setup_kernel(const float* __restrict__ qkv_w, const float* __restrict__ proj_w,
                             const float* __restrict__ fc1_w, const float* __restrict__ fc2_w,
                             const float* __restrict__ bt,
                             __half* __restrict__ wq, __half* __restrict__ wp,
                             __half* __restrict__ w1, __half* __restrict__ w2,
                             float* __restrict__ bf)
{
    int i = blockIdx.x * 256 + threadIdx.x;
    if (i < NWQ) { wq[i] = __float2half_rn(qkv_w[i]); return; }
    i -= NWQ;
    if (i < NWP) { wp[i] = __float2half_rn(proj_w[i]); return; }
    i -= NWP;
    if (i < NW1) { w1[i] = __float2half_rn(fc1_w[i]); return; }
    i -= NW1;
    if (i < NW2) { w2[i] = __float2half_rn(fc2_w[i]); return; }
    i -= NW2;
    if (i < NBF) {
        int h = i >> 14, rem = i & 16383, n = rem >> 7, m = rem & 127;
        int t1 = n >> 6, h1 = (n >> 3) & 7, w1i = n & 7;
        int t2 = m >> 6, h2 = (m >> 3) & 7, w2i = m & 7;
        int bi = (t1 - t2 + 1)*225 + (h1 - h2 + 7)*15 + (w1i - w2i + 7);
        bf[i] = bt[bi*HEADS + h];
    }
}

// ---------------- templated fp16 mma GEMM (3-stage cp.async) ---------------
#define BM 128
#define BK 64
#define PADH 72

template<int BN_, int WMG, int MF, int MINB>
__global__ __launch_bounds__(256, MINB)
void gemm_t(const __half* __restrict__ A, const __half* __restrict__ W,
            const float* __restrict__ bias, void* __restrict__ outv,
            int N, int K, int mode, const float* __restrict__ resid,
            const float* __restrict__ g2, const float* __restrict__ b2,
            __half* __restrict__ xw_out)
{
    constexpr int NF = 6;
    constexpr int STG_HALVES = (BM + BN_) * PADH;
    extern __shared__ __half smh[];
    __half* stg[3] = { smh, smh + STG_HALVES, smh + 2*STG_HALVES };

    int tid = threadIdx.x;
    int lane = tid & 31, wid = tid >> 5;
    int warp_m = wid % WMG, warp_n = wid / WMG;
    int col0 = blockIdx.x * BN_;
    int row0 = blockIdx.y * BM;
    int NC = K / BK;

    float acc[MF][NF][4];
    #pragma unroll
    for (int i = 0; i < MF; ++i)
        #pragma unroll
        for (int j = 0; j < NF; ++j)
            #pragma unroll
            for (int k = 0; k < 4; ++k) acc[i][j][k] = 0.f;

    int r0 = lane >> 2, c0 = lane & 3;

    int arow  = (lane & 7) + 8*((lane >> 3) & 1);
    int akoff = (lane >> 4) * 8;
    uint32_t aoff[MF];
    #pragma unroll
    for (int mf = 0; mf < MF; ++mf)
        aoff[mf] = (uint32_t)(((warp_m*(MF*16) + mf*16 + arow)*PADH + akoff) * 2);
    int bmat   = lane >> 3;
    int brow   = lane & 7;
    int bnhalf = bmat >> 1;
    int bkoff  = (bmat & 1) * 8;
    uint32_t boff[3];
    #pragma unroll
    for (int j = 0; j < 3; ++j)
        boff[j] = (uint32_t)(BM*PADH*2 +
                  ((warp_n*48 + (2*j + bnhalf)*8 + brow)*PADH + bkoff) * 2);

    auto load_tiles = [&](int kt, __half* stage) {
        uint32_t aA = smem_u32(stage), aB = smem_u32(stage + BM*PADH);
        #pragma unroll
        for (int j = 0; j < 4; ++j) {
            int idx = tid + j*256;
            int r = idx >> 3, c8 = idx & 7;
            cp_async16(aA + (uint32_t)(r*PADH + c8*8)*2, A + (size_t)(row0 + r)*K + kt + c8*8);
        }
        #pragma unroll
        for (int j = 0; j < BN_/32; ++j) {
            int idx = tid + j*256;
            int r = idx >> 3, c8 = idx & 7;
            cp_async16(aB + (uint32_t)(r*PADH + c8*8)*2, W + (size_t)(col0 + r)*K + kt + c8*8);
        }
    };

    // prologue: chunks 0,1
    load_tiles(0,  stg[0]); cp_commit();
    load_tiles(BK, stg[1]); cp_commit();

    for (int i = 0; i < NC; ++i) {
        cp_wait1();
        __syncthreads();
        if (i + 2 < NC)
            load_tiles((i+2)*BK, stg[(i+2)%3]);
        cp_commit();

        uint32_t base = smem_u32(stg[i % 3]);

        #pragma unroll
        for (int kk = 0; kk < 4; ++kk) {
            uint32_t kb = kk*16*2;
            uint32_t af[MF][4], bf[NF][2];
            #pragma unroll
            for (int mf = 0; mf < MF; ++mf)
                ldsm_x4(af[mf], base + aoff[mf] + kb);
            #pragma unroll
            for (int j = 0; j < 3; ++j) {
                uint32_t br[4];
                ldsm_x4(br, base + boff[j] + kb);
                bf[2*j  ][0] = br[0]; bf[2*j  ][1] = br[1];
                bf[2*j+1][0] = br[2]; bf[2*j+1][1] = br[3];
            }
            #pragma unroll
            for (int mf = 0; mf < MF; ++mf)
                #pragma unroll
                for (int nf = 0; nf < NF; ++nf)
                    mma_f16(acc[mf][nf], af[mf], bf[nf]);
        }
    }

    if (mode != 3) {
        #pragma unroll
        for (int mf = 0; mf < MF; ++mf) {
            #pragma unroll
            for (int half = 0; half < 2; ++half) {
                int gm = row0 + warp_m*(MF*16) + mf*16 + half*8 + r0;
                size_t rowbase = (size_t)gm * N;
                #pragma unroll
                for (int nf = 0; nf < NF; ++nf) {
                    int gn = col0 + warp_n*48 + nf*8 + c0*2;
                    float v0 = acc[mf][nf][half*2 + 0] + bias[gn];
                    float v1 = acc[mf][nf][half*2 + 1] + bias[gn + 1];
                    if (mode == 0) {
                        *(__half2*)((__half*)outv + rowbase + gn) = __floats2half2_rn(v0, v1);
                    } else if (mode == 1) {
                        *(__half2*)((__half*)outv + rowbase + gn) =
                            __floats2half2_rn(gelu_exact(v0), gelu_exact(v1));
                    } else {
                        const float2 rr = *(const float2*)(resid + rowbase + gn);
                        float2 o; o.x = v0 + rr.x; o.y = v1 + rr.y;
                        *(float2*)((float*)outv + rowbase + gn) = o;
                    }
                }
            }
        }
        return;
    }

    // ---- mode 3: x2 = proj + bias + shortcut, fused LN2 -> xw ----
    __syncthreads();
    float* redsum = (float*)smh;
    float* redsq  = (float*)smh + 128;
    if (tid < 128) { redsum[tid] = 0.f; redsq[tid] = 0.f; }
    __syncthreads();

    int toks[MF][2];
    #pragma unroll
    for (int mf = 0; mf < MF; ++mf) {
        #pragma unroll
        for (int half = 0; half < 2; ++half) {
            int gm = row0 + warp_m*(MF*16) + mf*16 + half*8 + r0;
            int win = gm >> 7, n = gm & 127;
            int bb = win >> 10, rem = win & 1023;
            int t = (rem >> 8)*2 + (n >> 6);
            int h = ((rem >> 4) & 15)*8 + ((n >> 3) & 7);
            int w = (rem & 15)*8 + (n & 7);
            int token = ((bb*TT + t)*HH + h)*WWD + w;
            toks[mf][half] = token;
            size_t rowbase = (size_t)token * CC;

            float psum = 0.f, psq = 0.f;
            #pragma unroll
            for (int nf = 0; nf < NF; ++nf) {
                int gn = col0 + warp_n*48 + nf*8 + c0*2;
                const float2 rr = *(const float2*)(resid + rowbase + gn);
                float v0 = acc[mf][nf][half*2+0] + bias[gn]   + rr.x;
                float v1 = acc[mf][nf][half*2+1] + bias[gn+1] + rr.y;
                acc[mf][nf][half*2+0] = v0;
                acc[mf][nf][half*2+1] = v1;
                float2 o; o.x = v0; o.y = v1;
                *(float2*)((float*)outv + rowbase + gn) = o;
                psum += v0 + v1;
                psq  += v0*v0 + v1*v1;
            }
            psum += __shfl_xor_sync(0xffffffffu, psum, 1);
            psum += __shfl_xor_sync(0xffffffffu, psum, 2);
            psq  += __shfl_xor_sync(0xffffffffu, psq, 1);
            psq  += __shfl_xor_sync(0xffffffffu, psq, 2);
            if (c0 == 0) {
                int lr = warp_m*(MF*16) + mf*16 + half*8 + r0;
                atomicAdd(&redsum[lr], psum);
                atomicAdd(&redsq[lr],  psq);
            }
        }
    }
    __syncthreads();

    #pragma unroll
    for (int mf = 0; mf < MF; ++mf) {
        #pragma unroll
        for (int half = 0; half < 2; ++half) {
            int lr = warp_m*(MF*16) + mf*16 + half*8 + r0;
            float mu  = redsum[lr] * (1.0f/192.0f);
            float var = redsq[lr] * (1.0f/192.0f) - mu*mu;
            float rinv = rsqrtf(var + 1e-5f);
            size_t rowbase = (size_t)toks[mf][half] * CC;
            #pragma unroll
            for (int nf = 0; nf < NF; ++nf) {
                int gn = col0 + warp_n*48 + nf*8 + c0*2;
                float n0 = (acc[mf][nf][half*2+0] - mu)*rinv*g2[gn]   + b2[gn];
                float n1 = (acc[mf][nf][half*2+1] - mu)*rinv*g2[gn+1] + b2[gn+1];
                *(__half2*)(xw_out + rowbase + gn) = __floats2half2_rn(n0, n1);
            }
        }
    }
}

#define GSMEM192 (3*(BM+192)*PADH*2)
#define GSMEM96  (3*(BM+96)*PADH*2)

// ---------------- attention (round-11 + stmatrix P store) -------------------
#define PQH 40
#define PPH 136
#define ATT_SMEM ((128*PPH + 32*PPH)*2)     // 43520 bytes

__global__ __launch_bounds__(256, 2)
void attn_mma(const __half* __restrict__ qkv,
              const float* __restrict__ biasf,
              __half* __restrict__ outp)
{
    extern __shared__ __half sh[];
    __half* Ps  = sh;
    __half* Qs  = sh;
    __half* Ks  = sh + 128*PQH;
    __half* Vts = sh + 128*PPH;

    int head = blockIdx.x, win = blockIdx.y;
    int tid = threadIdx.x, lane = tid & 31, w = tid >> 5;
    int r0 = lane >> 2, c0 = lane & 3;

    if (tid < 128) {
        const __half* rb = qkv + (size_t)win*NWTOK*QKVDIM + (size_t)tid*QKVDIM + head*HDIM;
        const uint4* q4 = (const uint4*)(rb);
        const uint4* k4 = (const uint4*)(rb + CC);
        uint4* qd = (uint4*)(Qs + tid*PQH);
        uint4* kd = (uint4*)(Ks + tid*PQH);
        qd[0] = q4[0]; qd[1] = q4[1]; qd[2] = q4[2]; qd[3] = q4[3];
        kd[0] = k4[0]; kd[1] = k4[1]; kd[2] = k4[2]; kd[3] = k4[3];
    } else {
        int tok = tid - 128;
        const uint4* v4 = (const uint4*)(qkv + (size_t)win*NWTOK*QKVDIM +
                                         (size_t)tok*QKVDIM + 2*CC + head*HDIM);
        #pragma unroll
        for (int q = 0; q < 4; ++q) {
            uint4 vv = v4[q];
            const __half* vh = (const __half*)&vv;
            #pragma unroll
            for (int d = 0; d < 8; ++d) Vts[(q*8 + d)*PPH + tok] = vh[d];
        }
    }
    __syncthreads();

    int arow  = (lane & 7) + 8*((lane >> 3) & 1);
    int akoff = (lane >> 4) * 8;
    int bmat  = lane >> 3, brow = lane & 7;
    int bnhalf = bmat >> 1, bkoff = (bmat & 1) * 8;
    uint32_t base = smem_u32(sh);

    float s[16][4];
    #pragma unroll
    for (int b = 0; b < 16; ++b)
        #pragma unroll
        for (int c = 0; c < 4; ++c) s[b][c] = 0.f;

    {
        uint32_t aoffQ = (uint32_t)(((w*16 + arow)*PQH + akoff) * 2);
        #pragma unroll
        for (int kk = 0; kk < 2; ++kk) {
            uint32_t kb = kk*32;
            uint32_t af[4];
            ldsm_x4(af, base + aoffQ + kb);
            #pragma unroll
            for (int j = 0; j < 8; ++j) {
                uint32_t br[4];
                uint32_t bo = (uint32_t)(128*PQH*2 +
                              (((2*j + bnhalf)*8 + brow)*PQH + bkoff) * 2);
                ldsm_x4(br, base + bo + kb);
                uint32_t b0[2] = { br[0], br[1] };
                uint32_t b1[2] = { br[2], br[3] };
                mma_f16(s[2*j  ], af, b0);
                mma_f16(s[2*j+1], af, b1);
            }
        }
    }

    float inv[2];
    const float* bh = biasf + (size_t)head*NWTOK*NWTOK;
    #pragma unroll
    for (int half = 0; half < 2; ++half) {
        int r = w*16 + half*8 + r0;
        const float2* brw = (const float2*)(bh + r*NWTOK) + c0;
        float mx = -1e30f;
        #pragma unroll
        for (int nf = 0; nf < 16; ++nf) {
            float2 bb = brw[nf*4];
            float v0 = s[nf][half*2+0]*ATTSCALE + bb.x;
            float v1 = s[nf][half*2+1]*ATTSCALE + bb.y;
            s[nf][half*2+0] = v0;
            s[nf][half*2+1] = v1;
            mx = fmaxf(mx, fmaxf(v0, v1));
        }
        mx = fmaxf(mx, __shfl_xor_sync(0xffffffffu, mx, 1));
        mx = fmaxf(mx, __shfl_xor_sync(0xffffffffu, mx, 2));
        float sum = 0.f;
        #pragma unroll
        for (int nf = 0; nf < 16; ++nf) {
            float e0 = __expf(s[nf][half*2+0] - mx);
            float e1 = __expf(s[nf][half*2+1] - mx);
            s[nf][half*2+0] = e0;
            s[nf][half*2+1] = e1;
            sum += e0 + e1;
        }
        sum += __shfl_xor_sync(0xffffffffu, sum, 1);
        sum += __shfl_xor_sync(0xffffffffu, sum, 2);
        inv[half] = 1.0f / sum;
    }

    __syncthreads();   // all warps done reading Qs/Ks before P overwrites

    // ---- store P via stmatrix: matrix m <- nf = 4m+t (2-way max conflicts) ----
    #pragma unroll
    for (int half = 0; half < 2; ++half) {
        int srow = w*16 + half*8 + (lane & 7);
        int mtx  = lane >> 3;
        #pragma unroll
        for (int t = 0; t < 4; ++t) {
            uint32_t addr = base + (uint32_t)((srow*PPH + (4*mtx + t)*8) * 2);
            stsm_x4(addr,
                    pack2(s[t    ][half*2+0], s[t    ][half*2+1]),
                    pack2(s[4+t  ][half*2+0], s[4+t  ][half*2+1]),
                    pack2(s[8+t  ][half*2+0], s[8+t  ][half*2+1]),
                    pack2(s[12+t ][half*2+0], s[12+t ][half*2+1]));
        }
    }
    __syncthreads();

    float o[4][4];
    #pragma unroll
    for (int b = 0; b < 4; ++b)
        #pragma unroll
        for (int c = 0; c < 4; ++c) o[b][c] = 0.f;

    {
        uint32_t aoffP = (uint32_t)(((w*16 + arow)*PPH + akoff) * 2);
        #pragma unroll
        for (int kk = 0; kk < 8; ++kk) {
            uint32_t kb = kk*32;
            uint32_t af[4];
            ldsm_x4(af, base + aoffP + kb);
            #pragma unroll
            for (int j = 0; j < 2; ++j) {
                uint32_t br[4];
                uint32_t bo = (uint32_t)(128*PPH*2 +
                              (((2*j + bnhalf)*8 + brow)*PPH + bkoff) * 2);
                ldsm_x4(br, base + bo + kb);
                uint32_t b0[2] = { br[0], br[1] };
                uint32_t b1[2] = { br[2], br[3] };
                mma_f16(o[2*j  ], af, b0);
                mma_f16(o[2*j+1], af, b1);
            }
        }
    }

    #pragma unroll
    for (int half = 0; half < 2; ++half) {
        int r = w*16 + half*8 + r0;
        float sc = inv[half];
        __half* op = outp + ((size_t)win*NWTOK + r)*CC + head*HDIM;
        #pragma unroll
        for (int nf = 0; nf < 4; ++nf)
            *(__half2*)(op + nf*8 + 2*c0) =
                __floats2half2_rn(o[nf][half*2+0]*sc, o[nf][half*2+1]*sc);
    }
}

// ---------------- launch ----------------
extern "C" void kernel_launch(void* const* d_in, const int* in_sizes, int n_in,
                              void* d_out, int out_size)
{
    const float* x        = (const float*)d_in[0];
    const float* norm1_g  = (const float*)d_in[1];
    const float* norm1_b  = (const float*)d_in[2];
    const float* qkv_w    = (const float*)d_in[3];
    const float* qkv_b    = (const float*)d_in[4];
    const float* bias_tab = (const float*)d_in[5];
    const float* proj_w   = (const float*)d_in[6];
    const float* proj_b   = (const float*)d_in[7];
    const float* norm2_g  = (const float*)d_in[8];
    const float* norm2_b  = (const float*)d_in[9];
    const float* fc1_w    = (const float*)d_in[10];
    const float* fc1_b    = (const float*)d_in[11];
    const float* fc2_w    = (const float*)d_in[12];
    const float* fc2_b    = (const float*)d_in[13];
    float* out = (float*)d_out;

    __half *xw, *qkvb, *attno, *h1, *wq, *wp, *w1, *w2;
    float *x2, *bf;
    cudaGetSymbolAddress((void**)&xw,    g_xw);
    cudaGetSymbolAddress((void**)&qkvb,  g_qkv);
    cudaGetSymbolAddress((void**)&attno, g_attnout);
    cudaGetSymbolAddress((void**)&x2,    g_x2);
    cudaGetSymbolAddress((void**)&h1,    g_h1);
    cudaGetSymbolAddress((void**)&wq,    g_wq);
    cudaGetSymbolAddress((void**)&wp,    g_wp);
    cudaGetSymbolAddress((void**)&w1,    g_w1);
    cudaGetSymbolAddress((void**)&w2,    g_w2);
    cudaGetSymbolAddress((void**)&bf,    g_biasf);

    cudaFuncSetAttribute(attn_mma, cudaFuncAttributeMaxDynamicSharedMemorySize, ATT_SMEM);
    cudaFuncSetAttribute(gemm_t<192,2,4,1>, cudaFuncAttributeMaxDynamicSharedMemorySize, GSMEM192);
    cudaFuncSetAttribute(gemm_t<96,4,2,2>,  cudaFuncAttributeMaxDynamicSharedMemorySize, GSMEM96);

    // merged setup
    setup_kernel<<<(NSETUP+255)/256, 256>>>(qkv_w, proj_w, fc1_w, fc2_w, bias_tab,
                                            wq, wp, w1, w2, bf);

    // 1. LN1 + window partition -> half
    ln_kernel<<<TOKENS/8, 256>>>(x, norm1_g, norm1_b, xw, 1);
    // 2. QKV GEMM -> half
    gemm_t<96,4,2,2><<<dim3(QKVDIM/96, TOKENS/BM), 256, GSMEM96>>>(xw, wq, qkv_b, qkvb,
        QKVDIM, CC, 0, nullptr, nullptr, nullptr, nullptr);
    // 3. windowed attention -> half
    attn_mma<<<dim3(HEADS, NWIN), 256, ATT_SMEM>>>(qkvb, bf, attno);
    // 4. proj + window-reverse + residual -> x2 (f32), fused LN2 -> xw (half)
    gemm_t<192,2,4,1><<<dim3(CC/192, TOKENS/BM), 256, GSMEM192>>>(attno, wp, proj_b, x2,
        CC, CC, 3, x, norm2_g, norm2_b, xw);
    // 5. FC1 + GELU -> half
    gemm_t<96,4,2,2><<<dim3(HIDDEN/96, TOKENS/BM), 256, GSMEM96>>>(xw, w1, fc1_b, h1,
        HIDDEN, CC, 1, nullptr, nullptr, nullptr, nullptr);
    // 6. FC2 + residual -> out (f32)
    gemm_t<96,4,2,2><<<dim3(CC/96, TOKENS/BM), 256, GSMEM96>>>(h1, w2, fc2_b, out,
        CC, HIDDEN, 2, x2, nullptr, nullptr, nullptr);
}

// round 16
// speedup vs baseline: 1.0145x; 1.0145x over previous
#include <cuda_runtime.h>
#include <cuda_fp16.h>
#include <math.h>
#include <stdint.h>

// ---------------- problem constants ----------------
#define BATCH 2
#define TT 8
#define HH 128
#define WWD 128
#define CC 192
#define TOKENS (BATCH*TT*HH*WWD)         // 262144
#define NWIN 2048
#define NWTOK 128
#define HEADS 6
#define HDIM 32
#define HIDDEN 768
#define QKVDIM 576
#define ATTSCALE 0.17677669529663687f

// ---------------- scratch ----------------
__device__ __half g_xw[(size_t)TOKENS * CC];
__device__ __half g_qkv[(size_t)NWIN * NWTOK * QKVDIM];
__device__ __half g_attnout[(size_t)TOKENS * CC];
__device__ float  g_x2[(size_t)TOKENS * CC];
__device__ __half g_h1[(size_t)TOKENS * HIDDEN];
__device__ __half g_wq[QKVDIM * CC];
__device__ __half g_wp[CC * CC];
__device__ __half g_w1[HIDDEN * CC];
__device__ __half g_w2[CC * HIDDEN];
__device__ __half g_biasf[HEADS * NWTOK * NWTOK];   // fragment-ordered half bias

// ---------------- helpers ----------------
__device__ __forceinline__ void cp_async16(uint32_t dst, const void* src) {
    asm volatile("cp.async.cg.shared.global [%0], [%1], 16;" :: "r"(dst), "l"(src));
}
__device__ __forceinline__ void cp_commit() { asm volatile("cp.async.commit_group;"); }
__device__ __forceinline__ void cp_wait1()  { asm volatile("cp.async.wait_group 1;"); }
__device__ __forceinline__ uint32_t smem_u32(const void* p) {
    uint32_t a;
    asm("{ .reg .u64 t; cvta.to.shared.u64 t, %1; cvt.u32.u64 %0, t; }" : "=r"(a) : "l"(p));
    return a;
}
__device__ __forceinline__ void mma_f16(float c[4], const uint32_t a[4], const uint32_t b[2]) {
    asm volatile(
        "mma.sync.aligned.m16n8k16.row.col.f32.f16.f16.f32 "
        "{%0,%1,%2,%3}, {%4,%5,%6,%7}, {%8,%9}, {%0,%1,%2,%3};"
        : "+f"(c[0]), "+f"(c[1]), "+f"(c[2]), "+f"(c[3])
        : "r"(a[0]), "r"(a[1]), "r"(a[2]), "r"(a[3]), "r"(b[0]), "r"(b[1]));
}
__device__ __forceinline__ void ldsm_x4(uint32_t r[4], uint32_t addr) {
    asm volatile("ldmatrix.sync.aligned.m8n8.x4.shared.b16 {%0,%1,%2,%3}, [%4];"
        : "=r"(r[0]), "=r"(r[1]), "=r"(r[2]), "=r"(r[3]) : "r"(addr));
}
__device__ __forceinline__ void stsm_x4(uint32_t addr, uint32_t r0, uint32_t r1,
                                        uint32_t r2, uint32_t r3) {
    asm volatile("stmatrix.sync.aligned.m8n8.x4.shared.b16 [%0], {%1,%2,%3,%4};"
        :: "r"(addr), "r"(r0), "r"(r1), "r"(r2), "r"(r3) : "memory");
}
__device__ __forceinline__ uint32_t pack2(float x, float y) {
    __half2 h = __floats2half2_rn(x, y);
    return *(uint32_t*)&h;
}
__device__ __forceinline__ float gelu_exact(float x) {
    return 0.5f * x * (1.0f + erff(x * 0.70710678118654752f));
}

// ---------------- LayerNorm -> half (window scatter), float2 I/O ------------
__global__ void ln_kernel(const float* __restrict__ in,
                          const float* __restrict__ g,
                          const float* __restrict__ b,
                          __half* __restrict__ out, int windowed)
{
    int token = (blockIdx.x << 3) + (threadIdx.x >> 5);
    int lane  = threadIdx.x & 31;
    size_t base = (size_t)token * CC;

    const float2* inp = (const float2*)(in + base);
    float2 v[3]; float s = 0.f;
    #pragma unroll
    for (int j = 0; j < 3; ++j) { v[j] = inp[lane + 32*j]; s += v[j].x + v[j].y; }
    #pragma unroll
    for (int o = 16; o; o >>= 1) s += __shfl_xor_sync(0xffffffffu, s, o);
    float mu = s * (1.0f/192.0f);
    float vs = 0.f;
    #pragma unroll
    for (int j = 0; j < 3; ++j) {
        float d0 = v[j].x - mu, d1 = v[j].y - mu;
        vs += d0*d0 + d1*d1;
    }
    #pragma unroll
    for (int o = 16; o; o >>= 1) vs += __shfl_xor_sync(0xffffffffu, vs, o);
    float rinv = rsqrtf(vs * (1.0f/192.0f) + 1e-5f);

    size_t obase;
    if (windowed) {
        int w = token & 127, h = (token >> 7) & 127, t = (token >> 14) & 7, bb = token >> 17;
        int win = ((bb*4 + (t >> 1))*16 + (h >> 3))*16 + (w >> 3);
        int n   = ((t & 1) << 6) | ((h & 7) << 3) | (w & 7);
        obase = ((size_t)win * NWTOK + n) * CC;
    } else obase = base;
    #pragma unroll
    for (int j = 0; j < 3; ++j) {
        int c = (lane + 32*j)*2;
        const float2 gg = *(const float2*)(g + c);
        const float2 bb = *(const float2*)(b + c);
        float n0 = (v[j].x - mu)*rinv*gg.x + bb.x;
        float n1 = (v[j].y - mu)*rinv*gg.y + bb.y;
        *(__half2*)(out + obase + c) = __floats2half2_rn(n0, n1);
    }
}

// ---------------- merged setup ----------------
#define NWQ (QKVDIM*CC)
#define NWP (CC*CC)
#define NW1 (HIDDEN*CC)
#define NW2 (CC*HIDDEN)
#define NBF (HEADS*NWTOK*NWTOK)
#define NSETUP (NWQ+NWP+NW1+NW2+NBF)

__global__ void setup_kernel(const float* __restrict__ qkv_w, const float* __restrict__ proj_w,
                             const float* __restrict__ fc1_w, const float* __restrict__ fc2_w,
                             const float* __restrict__ bt,
                             __half* __restrict__ wq, __half* __restrict__ wp,
                             __half* __restrict__ w1, __half* __restrict__ w2,
                             __half* __restrict__ bf)
{
    int i = blockIdx.x * 256 + threadIdx.x;
    if (i < NWQ) { wq[i] = __float2half_rn(qkv_w[i]); return; }
    i -= NWQ;
    if (i < NWP) { wp[i] = __float2half_rn(proj_w[i]); return; }
    i -= NWP;
    if (i < NW1) { w1[i] = __float2half_rn(fc1_w[i]); return; }
    i -= NW1;
    if (i < NW2) { w2[i] = __float2half_rn(fc2_w[i]); return; }
    i -= NW2;
    if (i < NBF) {
        // fragment-ordered half: [head][row r][c0][t] with t = nf*2+jj
        int h = i >> 14, rem = i & 16383;
        int r = rem >> 7, q = rem & 127;
        int c0 = q >> 5, t = q & 31;
        int nf = t >> 1, jj = t & 1;
        int m = nf*8 + c0*2 + jj;      // attended column
        int t1 = r >> 6, h1 = (r >> 3) & 7, w1i = r & 7;
        int t2 = m >> 6, h2 = (m >> 3) & 7, w2i = m & 7;
        int bi = (t1 - t2 + 1)*225 + (h1 - h2 + 7)*15 + (w1i - w2i + 7);
        bf[i] = __float2half_rn(bt[bi*HEADS + h]);
    }
}

// ---------------- templated fp16 mma GEMM (3-stage cp.async) ---------------
// modes: 0 plain->half (Q channels pre-scaled)  1 GELU->half  2 +resid->f32
//        3 +win-reverse +resid->f32 AND fused LN2 -> half xw (BN_=192 only)
#define BM 128
#define BK 64
#define PADH 72

template<int BN_, int WMG, int MF, int MINB>
__global__ __launch_bounds__(256, MINB)
void gemm_t(const __half* __restrict__ A, const __half* __restrict__ W,
            const float* __restrict__ bias, void* __restrict__ outv,
            int N, int K, int mode, const float* __restrict__ resid,
            const float* __restrict__ g2, const float* __restrict__ b2,
            __half* __restrict__ xw_out)
{
    constexpr int NF = 6;
    constexpr int STG_HALVES = (BM + BN_) * PADH;
    extern __shared__ __half smh[];
    __half* stg[3] = { smh, smh + STG_HALVES, smh + 2*STG_HALVES };

    int tid = threadIdx.x;
    int lane = tid & 31, wid = tid >> 5;
    int warp_m = wid % WMG, warp_n = wid / WMG;
    int col0 = blockIdx.x * BN_;
    int row0 = blockIdx.y * BM;
    int NC = K / BK;

    float acc[MF][NF][4];
    #pragma unroll
    for (int i = 0; i < MF; ++i)
        #pragma unroll
        for (int j = 0; j < NF; ++j)
            #pragma unroll
            for (int k = 0; k < 4; ++k) acc[i][j][k] = 0.f;

    int r0 = lane >> 2, c0 = lane & 3;

    int arow  = (lane & 7) + 8*((lane >> 3) & 1);
    int akoff = (lane >> 4) * 8;
    uint32_t aoff[MF];
    #pragma unroll
    for (int mf = 0; mf < MF; ++mf)
        aoff[mf] = (uint32_t)(((warp_m*(MF*16) + mf*16 + arow)*PADH + akoff) * 2);
    int bmat   = lane >> 3;
    int brow   = lane & 7;
    int bnhalf = bmat >> 1;
    int bkoff  = (bmat & 1) * 8;
    uint32_t boff[3];
    #pragma unroll
    for (int j = 0; j < 3; ++j)
        boff[j] = (uint32_t)(BM*PADH*2 +
                  ((warp_n*48 + (2*j + bnhalf)*8 + brow)*PADH + bkoff) * 2);

    auto load_tiles = [&](int kt, __half* stage) {
        uint32_t aA = smem_u32(stage), aB = smem_u32(stage + BM*PADH);
        #pragma unroll
        for (int j = 0; j < 4; ++j) {
            int idx = tid + j*256;
            int r = idx >> 3, c8 = idx & 7;
            cp_async16(aA + (uint32_t)(r*PADH + c8*8)*2, A + (size_t)(row0 + r)*K + kt + c8*8);
        }
        #pragma unroll
        for (int j = 0; j < BN_/32; ++j) {
            int idx = tid + j*256;
            int r = idx >> 3, c8 = idx & 7;
            cp_async16(aB + (uint32_t)(r*PADH + c8*8)*2, W + (size_t)(col0 + r)*K + kt + c8*8);
        }
    };

    load_tiles(0,  stg[0]); cp_commit();
    load_tiles(BK, stg[1]); cp_commit();

    for (int i = 0; i < NC; ++i) {
        cp_wait1();
        __syncthreads();
        if (i + 2 < NC)
            load_tiles((i+2)*BK, stg[(i+2)%3]);
        cp_commit();

        uint32_t base = smem_u32(stg[i % 3]);

        #pragma unroll
        for (int kk = 0; kk < 4; ++kk) {
            uint32_t kb = kk*16*2;
            uint32_t af[MF][4], bf[NF][2];
            #pragma unroll
            for (int mf = 0; mf < MF; ++mf)
                ldsm_x4(af[mf], base + aoff[mf] + kb);
            #pragma unroll
            for (int j = 0; j < 3; ++j) {
                uint32_t br[4];
                ldsm_x4(br, base + boff[j] + kb);
                bf[2*j  ][0] = br[0]; bf[2*j  ][1] = br[1];
                bf[2*j+1][0] = br[2]; bf[2*j+1][1] = br[3];
            }
            #pragma unroll
            for (int mf = 0; mf < MF; ++mf)
                #pragma unroll
                for (int nf = 0; nf < NF; ++nf)
                    mma_f16(acc[mf][nf], af[mf], bf[nf]);
        }
    }

    if (mode != 3) {
        #pragma unroll
        for (int mf = 0; mf < MF; ++mf) {
            #pragma unroll
            for (int half = 0; half < 2; ++half) {
                int gm = row0 + warp_m*(MF*16) + mf*16 + half*8 + r0;
                size_t rowbase = (size_t)gm * N;
                #pragma unroll
                for (int nf = 0; nf < NF; ++nf) {
                    int gn = col0 + warp_n*48 + nf*8 + c0*2;
                    float v0 = acc[mf][nf][half*2 + 0] + bias[gn];
                    float v1 = acc[mf][nf][half*2 + 1] + bias[gn + 1];
                    if (mode == 0) {
                        if (gn < CC) { v0 *= ATTSCALE; v1 *= ATTSCALE; }   // pre-scale Q
                        *(__half2*)((__half*)outv + rowbase + gn) = __floats2half2_rn(v0, v1);
                    } else if (mode == 1) {
                        *(__half2*)((__half*)outv + rowbase + gn) =
                            __floats2half2_rn(gelu_exact(v0), gelu_exact(v1));
                    } else {
                        const float2 rr = *(const float2*)(resid + rowbase + gn);
                        float2 o; o.x = v0 + rr.x; o.y = v1 + rr.y;
                        *(float2*)((float*)outv + rowbase + gn) = o;
                    }
                }
            }
        }
        return;
    }

    // ---- mode 3: x2 = proj + bias + shortcut, fused LN2 -> xw ----
    __syncthreads();
    float* redsum = (float*)smh;
    float* redsq  = (float*)smh + 128;
    if (tid < 128) { redsum[tid] = 0.f; redsq[tid] = 0.f; }
    __syncthreads();

    int toks[MF][2];
    #pragma unroll
    for (int mf = 0; mf < MF; ++mf) {
        #pragma unroll
        for (int half = 0; half < 2; ++half) {
            int gm = row0 + warp_m*(MF*16) + mf*16 + half*8 + r0;
            int win = gm >> 7, n = gm & 127;
            int bb = win >> 10, rem = win & 1023;
            int t = (rem >> 8)*2 + (n >> 6);
            int h = ((rem >> 4) & 15)*8 + ((n >> 3) & 7);
            int w = (rem & 15)*8 + (n & 7);
            int token = ((bb*TT + t)*HH + h)*WWD + w;
            toks[mf][half] = token;
            size_t rowbase = (size_t)token * CC;

            float psum = 0.f, psq = 0.f;
            #pragma unroll
            for (int nf = 0; nf < NF; ++nf) {
                int gn = col0 + warp_n*48 + nf*8 + c0*2;
                const float2 rr = *(const float2*)(resid + rowbase + gn);
                float v0 = acc[mf][nf][half*2+0] + bias[gn]   + rr.x;
                float v1 = acc[mf][nf][half*2+1] + bias[gn+1] + rr.y;
                acc[mf][nf][half*2+0] = v0;
                acc[mf][nf][half*2+1] = v1;
                float2 o; o.x = v0; o.y = v1;
                *(float2*)((float*)outv + rowbase + gn) = o;
                psum += v0 + v1;
                psq  += v0*v0 + v1*v1;
            }
            psum += __shfl_xor_sync(0xffffffffu, psum, 1);
            psum += __shfl_xor_sync(0xffffffffu, psum, 2);
            psq  += __shfl_xor_sync(0xffffffffu, psq, 1);
            psq  += __shfl_xor_sync(0xffffffffu, psq, 2);
            if (c0 == 0) {
                int lr = warp_m*(MF*16) + mf*16 + half*8 + r0;
                atomicAdd(&redsum[lr], psum);
                atomicAdd(&redsq[lr],  psq);
            }
        }
    }
    __syncthreads();

    #pragma unroll
    for (int mf = 0; mf < MF; ++mf) {
        #pragma unroll
        for (int half = 0; half < 2; ++half) {
            int lr = warp_m*(MF*16) + mf*16 + half*8 + r0;
            float mu  = redsum[lr] * (1.0f/192.0f);
            float var = redsq[lr] * (1.0f/192.0f) - mu*mu;
            float rinv = rsqrtf(var + 1e-5f);
            size_t rowbase = (size_t)toks[mf][half] * CC;
            #pragma unroll
            for (int nf = 0; nf < NF; ++nf) {
                int gn = col0 + warp_n*48 + nf*8 + c0*2;
                float n0 = (acc[mf][nf][half*2+0] - mu)*rinv*g2[gn]   + b2[gn];
                float n1 = (acc[mf][nf][half*2+1] - mu)*rinv*g2[gn+1] + b2[gn+1];
                *(__half2*)(xw_out + rowbase + gn) = __floats2half2_rn(n0, n1);
            }
        }
    }
}

#define GSMEM192 (3*(BM+192)*PADH*2)
#define GSMEM96  (3*(BM+96)*PADH*2)

// ---------------- attention (half fragment-ordered bias; Q pre-scaled) ------
#define PQH 40
#define PPH 136
#define ATT_SMEM ((128*PPH + 32*PPH)*2)     // 43520 bytes

__global__ __launch_bounds__(256, 2)
void attn_mma(const __half* __restrict__ qkv,
              const __half* __restrict__ biasf,
              __half* __restrict__ outp)
{
    extern __shared__ __half sh[];
    __half* Ps  = sh;
    __half* Qs  = sh;
    __half* Ks  = sh + 128*PQH;
    __half* Vts = sh + 128*PPH;

    int head = blockIdx.x, win = blockIdx.y;
    int tid = threadIdx.x, lane = tid & 31, w = tid >> 5;
    int r0 = lane >> 2, c0 = lane & 3;

    if (tid < 128) {
        const __half* rb = qkv + (size_t)win*NWTOK*QKVDIM + (size_t)tid*QKVDIM + head*HDIM;
        const uint4* q4 = (const uint4*)(rb);
        const uint4* k4 = (const uint4*)(rb + CC);
        uint4* qd = (uint4*)(Qs + tid*PQH);
        uint4* kd = (uint4*)(Ks + tid*PQH);
        qd[0] = q4[0]; qd[1] = q4[1]; qd[2] = q4[2]; qd[3] = q4[3];
        kd[0] = k4[0]; kd[1] = k4[1]; kd[2] = k4[2]; kd[3] = k4[3];
    } else {
        int tok = tid - 128;
        const uint4* v4 = (const uint4*)(qkv + (size_t)win*NWTOK*QKVDIM +
                                         (size_t)tok*QKVDIM + 2*CC + head*HDIM);
        #pragma unroll
        for (int q = 0; q < 4; ++q) {
            uint4 vv = v4[q];
            const __half* vh = (const __half*)&vv;
            #pragma unroll
            for (int d = 0; d < 8; ++d) Vts[(q*8 + d)*PPH + tok] = vh[d];
        }
    }
    __syncthreads();

    int arow  = (lane & 7) + 8*((lane >> 3) & 1);
    int akoff = (lane >> 4) * 8;
    int bmat  = lane >> 3, brow = lane & 7;
    int bnhalf = bmat >> 1, bkoff = (bmat & 1) * 8;
    uint32_t base = smem_u32(sh);

    float s[16][4];
    #pragma unroll
    for (int b = 0; b < 16; ++b)
        #pragma unroll
        for (int c = 0; c < 4; ++c) s[b][c] = 0.f;

    {
        uint32_t aoffQ = (uint32_t)(((w*16 + arow)*PQH + akoff) * 2);
        #pragma unroll
        for (int kk = 0; kk < 2; ++kk) {
            uint32_t kb = kk*32;
            uint32_t af[4];
            ldsm_x4(af, base + aoffQ + kb);
            #pragma unroll
            for (int j = 0; j < 8; ++j) {
                uint32_t br[4];
                uint32_t bo = (uint32_t)(128*PQH*2 +
                              (((2*j + bnhalf)*8 + brow)*PQH + bkoff) * 2);
                ldsm_x4(br, base + bo + kb);
                uint32_t b0[2] = { br[0], br[1] };
                uint32_t b1[2] = { br[2], br[3] };
                mma_f16(s[2*j  ], af, b0);
                mma_f16(s[2*j+1], af, b1);
            }
        }
    }

    // ---- half fragment-ordered bias + row softmax (Q pre-scaled) ----
    float inv[2];
    #pragma unroll
    for (int half = 0; half < 2; ++half) {
        int r = w*16 + half*8 + r0;
        const uint4* bp = (const uint4*)(biasf +
                           (((size_t)head*128 + r)*4 + c0)*32);
        float mx = -1e30f;
        #pragma unroll
        for (int q = 0; q < 4; ++q) {           // 4 x uint4 = 32 halves = t 0..31
            uint4 raw = bp[q];
            const __half2* hp = (const __half2*)&raw;
            #pragma unroll
            for (int p = 0; p < 4; ++p) {       // pair p covers t = q*8+p*2, +1
                int nf = q*4 + p;               // t/2 = nf index
                float2 bb = __half22float2(hp[p]);
                float v0 = s[nf][half*2+0] + bb.x;
                float v1 = s[nf][half*2+1] + bb.y;
                s[nf][half*2+0] = v0;
                s[nf][half*2+1] = v1;
                mx = fmaxf(mx, fmaxf(v0, v1));
            }
        }
        mx = fmaxf(mx, __shfl_xor_sync(0xffffffffu, mx, 1));
        mx = fmaxf(mx, __shfl_xor_sync(0xffffffffu, mx, 2));
        float sum = 0.f;
        #pragma unroll
        for (int nf = 0; nf < 16; ++nf) {
            float e0 = __expf(s[nf][half*2+0] - mx);
            float e1 = __expf(s[nf][half*2+1] - mx);
            s[nf][half*2+0] = e0;
            s[nf][half*2+1] = e1;
            sum += e0 + e1;
        }
        sum += __shfl_xor_sync(0xffffffffu, sum, 1);
        sum += __shfl_xor_sync(0xffffffffu, sum, 2);
        inv[half] = 1.0f / sum;
    }

    __syncthreads();   // all warps done reading Qs/Ks before P overwrites

    // ---- store P via stmatrix ----
    #pragma unroll
    for (int half = 0; half < 2; ++half) {
        int srow = w*16 + half*8 + (lane & 7);
        int mtx  = lane >> 3;
        #pragma unroll
        for (int t = 0; t < 4; ++t) {
            uint32_t addr = base + (uint32_t)((srow*PPH + (4*mtx + t)*8) * 2);
            stsm_x4(addr,
                    pack2(s[t    ][half*2+0], s[t    ][half*2+1]),
                    pack2(s[4+t  ][half*2+0], s[4+t  ][half*2+1]),
                    pack2(s[8+t  ][half*2+0], s[8+t  ][half*2+1]),
                    pack2(s[12+t ][half*2+0], s[12+t ][half*2+1]));
        }
    }
    __syncthreads();

    float o[4][4];
    #pragma unroll
    for (int b = 0; b < 4; ++b)
        #pragma unroll
        for (int c = 0; c < 4; ++c) o[b][c] = 0.f;

    {
        uint32_t aoffP = (uint32_t)(((w*16 + arow)*PPH + akoff) * 2);
        #pragma unroll
        for (int kk = 0; kk < 8; ++kk) {
            uint32_t kb = kk*32;
            uint32_t af[4];
            ldsm_x4(af, base + aoffP + kb);
            #pragma unroll
            for (int j = 0; j < 2; ++j) {
                uint32_t br[4];
                uint32_t bo = (uint32_t)(128*PPH*2 +
                              (((2*j + bnhalf)*8 + brow)*PPH + bkoff) * 2);
                ldsm_x4(br, base + bo + kb);
                uint32_t b0[2] = { br[0], br[1] };
                uint32_t b1[2] = { br[2], br[3] };
                mma_f16(o[2*j  ], af, b0);
                mma_f16(o[2*j+1], af, b1);
            }
        }
    }

    #pragma unroll
    for (int half = 0; half < 2; ++half) {
        int r = w*16 + half*8 + r0;
        float sc = inv[half];
        __half* op = outp + ((size_t)win*NWTOK + r)*CC + head*HDIM;
        #pragma unroll
        for (int nf = 0; nf < 4; ++nf)
            *(__half2*)(op + nf*8 + 2*c0) =
                __floats2half2_rn(o[nf][half*2+0]*sc, o[nf][half*2+1]*sc);
    }
}

// ---------------- launch ----------------
extern "C" void kernel_launch(void* const* d_in, const int* in_sizes, int n_in,
                              void* d_out, int out_size)
{
    const float* x        = (const float*)d_in[0];
    const float* norm1_g  = (const float*)d_in[1];
    const float* norm1_b  = (const float*)d_in[2];
    const float* qkv_w    = (const float*)d_in[3];
    const float* qkv_b    = (const float*)d_in[4];
    const float* bias_tab = (const float*)d_in[5];
    const float* proj_w   = (const float*)d_in[6];
    const float* proj_b   = (const float*)d_in[7];
    const float* norm2_g  = (const float*)d_in[8];
    const float* norm2_b  = (const float*)d_in[9];
    const float* fc1_w    = (const float*)d_in[10];
    const float* fc1_b    = (const float*)d_in[11];
    const float* fc2_w    = (const float*)d_in[12];
    const float* fc2_b    = (const float*)d_in[13];
    float* out = (float*)d_out;

    __half *xw, *qkvb, *attno, *h1, *wq, *wp, *w1, *w2, *bf;
    float *x2;
    cudaGetSymbolAddress((void**)&xw,    g_xw);
    cudaGetSymbolAddress((void**)&qkvb,  g_qkv);
    cudaGetSymbolAddress((void**)&attno, g_attnout);
    cudaGetSymbolAddress((void**)&x2,    g_x2);
    cudaGetSymbolAddress((void**)&h1,    g_h1);
    cudaGetSymbolAddress((void**)&wq,    g_wq);
    cudaGetSymbolAddress((void**)&wp,    g_wp);
    cudaGetSymbolAddress((void**)&w1,    g_w1);
    cudaGetSymbolAddress((void**)&w2,    g_w2);
    cudaGetSymbolAddress((void**)&bf,    g_biasf);

    cudaFuncSetAttribute(attn_mma, cudaFuncAttributeMaxDynamicSharedMemorySize, ATT_SMEM);
    cudaFuncSetAttribute(gemm_t<192,2,4,1>, cudaFuncAttributeMaxDynamicSharedMemorySize, GSMEM192);
    cudaFuncSetAttribute(gemm_t<96,4,2,2>,  cudaFuncAttributeMaxDynamicSharedMemorySize, GSMEM96);

    // merged setup
    setup_kernel<<<(NSETUP+255)/256, 256>>>(qkv_w, proj_w, fc1_w, fc2_w, bias_tab,
                                            wq, wp, w1, w2, bf);

    // 1. LN1 + window partition -> half
    ln_kernel<<<TOKENS/8, 256>>>(x, norm1_g, norm1_b, xw, 1);
    // 2. QKV GEMM -> half (Q channels pre-scaled by ATTSCALE)
    gemm_t<96,4,2,2><<<dim3(QKVDIM/96, TOKENS/BM), 256, GSMEM96>>>(xw, wq, qkv_b, qkvb,
        QKVDIM, CC, 0, nullptr, nullptr, nullptr, nullptr);
    // 3. windowed attention -> half
    attn_mma<<<dim3(HEADS, NWIN), 256, ATT_SMEM>>>(qkvb, bf, attno);
    // 4. proj + window-reverse + residual -> x2 (f32), fused LN2 -> xw (half)
    gemm_t<192,2,4,1><<<dim3(CC/192, TOKENS/BM), 256, GSMEM192>>>(attno, wp, proj_b, x2,
        CC, CC, 3, x, norm2_g, norm2_b, xw);
    // 5. FC1 + GELU -> half
    gemm_t<96,4,2,2><<<dim3(HIDDEN/96, TOKENS/BM), 256, GSMEM96>>>(xw, w1, fc1_b, h1,
        HIDDEN, CC, 1, nullptr, nullptr, nullptr, nullptr);
    // 6. FC2 + residual -> out (f32)
    gemm_t<96,4,2,2><<<dim3(CC/96, TOKENS/BM), 256, GSMEM96>>>(h1, w2, fc2_b, out,
        CC, HIDDEN, 2, x2, nullptr, nullptr, nullptr);
}

// round 17
// speedup vs baseline: 1.0262x; 1.0115x over previous
#include <cuda_runtime.h>
#include <cuda_fp16.h>
#include <math.h>
#include <stdint.h>

// ---------------- problem constants ----------------
#define BATCH 2
#define TT 8
#define HH 128
#define WWD 128
#define CC 192
#define TOKENS (BATCH*TT*HH*WWD)         // 262144
#define NWIN 2048
#define NWTOK 128
#define HEADS 6
#define HDIM 32
#define HIDDEN 768
#define QKVDIM 576
#define ATTSCALE 0.17677669529663687f

// ---------------- scratch ----------------
__device__ __half g_xw[(size_t)TOKENS * CC];
__device__ __half g_qkv[(size_t)NWIN * NWTOK * QKVDIM];
__device__ __half g_attnout[(size_t)TOKENS * CC];
__device__ float  g_x2[(size_t)TOKENS * CC];
__device__ __half g_h1[(size_t)TOKENS * HIDDEN];
__device__ __half g_wq[QKVDIM * CC];
__device__ __half g_wp[CC * CC];
__device__ __half g_w1[HIDDEN * CC];
__device__ __half g_w2[CC * HIDDEN];
__device__ __half g_biasf[HEADS * NWTOK * NWTOK];   // fragment-ordered half bias

// ---------------- helpers ----------------
__device__ __forceinline__ void cp_async16(uint32_t dst, const void* src) {
    asm volatile("cp.async.cg.shared.global [%0], [%1], 16;" :: "r"(dst), "l"(src));
}
__device__ __forceinline__ void cp_commit() { asm volatile("cp.async.commit_group;"); }
__device__ __forceinline__ void cp_wait1()  { asm volatile("cp.async.wait_group 1;"); }
__device__ __forceinline__ void cp_wait0()  { asm volatile("cp.async.wait_group 0;"); }
__device__ __forceinline__ uint32_t smem_u32(const void* p) {
    uint32_t a;
    asm("{ .reg .u64 t; cvta.to.shared.u64 t, %1; cvt.u32.u64 %0, t; }" : "=r"(a) : "l"(p));
    return a;
}
__device__ __forceinline__ void mma_f16(float c[4], const uint32_t a[4], const uint32_t b[2]) {
    asm volatile(
        "mma.sync.aligned.m16n8k16.row.col.f32.f16.f16.f32 "
        "{%0,%1,%2,%3}, {%4,%5,%6,%7}, {%8,%9}, {%0,%1,%2,%3};"
        : "+f"(c[0]), "+f"(c[1]), "+f"(c[2]), "+f"(c[3])
        : "r"(a[0]), "r"(a[1]), "r"(a[2]), "r"(a[3]), "r"(b[0]), "r"(b[1]));
}
__device__ __forceinline__ void ldsm_x4(uint32_t r[4], uint32_t addr) {
    asm volatile("ldmatrix.sync.aligned.m8n8.x4.shared.b16 {%0,%1,%2,%3}, [%4];"
        : "=r"(r[0]), "=r"(r[1]), "=r"(r[2]), "=r"(r[3]) : "r"(addr));
}
__device__ __forceinline__ void stsm_x4(uint32_t addr, uint32_t r0, uint32_t r1,
                                        uint32_t r2, uint32_t r3) {
    asm volatile("stmatrix.sync.aligned.m8n8.x4.shared.b16 [%0], {%1,%2,%3,%4};"
        :: "r"(addr), "r"(r0), "r"(r1), "r"(r2), "r"(r3) : "memory");
}
__device__ __forceinline__ uint32_t pack2(float x, float y) {
    __half2 h = __floats2half2_rn(x, y);
    return *(uint32_t*)&h;
}
__device__ __forceinline__ float gelu_exact(float x) {
    return 0.5f * x * (1.0f + erff(x * 0.70710678118654752f));
}

// ---------------- LayerNorm -> half (window scatter), float2 I/O ------------
__global__ void ln_kernel(const float* __restrict__ in,
                          const float* __restrict__ g,
                          const float* __restrict__ b,
                          __half* __restrict__ out, int windowed)
{
    int token = (blockIdx.x << 3) + (threadIdx.x >> 5);
    int lane  = threadIdx.x & 31;
    size_t base = (size_t)token * CC;

    const float2* inp = (const float2*)(in + base);
    float2 v[3]; float s = 0.f;
    #pragma unroll
    for (int j = 0; j < 3; ++j) { v[j] = inp[lane + 32*j]; s += v[j].x + v[j].y; }
    #pragma unroll
    for (int o = 16; o; o >>= 1) s += __shfl_xor_sync(0xffffffffu, s, o);
    float mu = s * (1.0f/192.0f);
    float vs = 0.f;
    #pragma unroll
    for (int j = 0; j < 3; ++j) {
        float d0 = v[j].x - mu, d1 = v[j].y - mu;
        vs += d0*d0 + d1*d1;
    }
    #pragma unroll
    for (int o = 16; o; o >>= 1) vs += __shfl_xor_sync(0xffffffffu, vs, o);
    float rinv = rsqrtf(vs * (1.0f/192.0f) + 1e-5f);

    size_t obase;
    if (windowed) {
        int w = token & 127, h = (token >> 7) & 127, t = (token >> 14) & 7, bb = token >> 17;
        int win = ((bb*4 + (t >> 1))*16 + (h >> 3))*16 + (w >> 3);
        int n   = ((t & 1) << 6) | ((h & 7) << 3) | (w & 7);
        obase = ((size_t)win * NWTOK + n) * CC;
    } else obase = base;
    #pragma unroll
    for (int j = 0; j < 3; ++j) {
        int c = (lane + 32*j)*2;
        const float2 gg = *(const float2*)(g + c);
        const float2 bb = *(const float2*)(b + c);
        float n0 = (v[j].x - mu)*rinv*gg.x + bb.x;
        float n1 = (v[j].y - mu)*rinv*gg.y + bb.y;
        *(__half2*)(out + obase + c) = __floats2half2_rn(n0, n1);
    }
}

// ---------------- merged setup ----------------
#define NWQ (QKVDIM*CC)
#define NWP (CC*CC)
#define NW1 (HIDDEN*CC)
#define NW2 (CC*HIDDEN)
#define NBF (HEADS*NWTOK*NWTOK)
#define NSETUP (NWQ+NWP+NW1+NW2+NBF)

__global__ void setup_kernel(const float* __restrict__ qkv_w, const float* __restrict__ proj_w,
                             const float* __restrict__ fc1_w, const float* __restrict__ fc2_w,
                             const float* __restrict__ bt,
                             __half* __restrict__ wq, __half* __restrict__ wp,
                             __half* __restrict__ w1, __half* __restrict__ w2,
                             __half* __restrict__ bf)
{
    int i = blockIdx.x * 256 + threadIdx.x;
    if (i < NWQ) { wq[i] = __float2half_rn(qkv_w[i]); return; }
    i -= NWQ;
    if (i < NWP) { wp[i] = __float2half_rn(proj_w[i]); return; }
    i -= NWP;
    if (i < NW1) { w1[i] = __float2half_rn(fc1_w[i]); return; }
    i -= NW1;
    if (i < NW2) { w2[i] = __float2half_rn(fc2_w[i]); return; }
    i -= NW2;
    if (i < NBF) {
        // fragment-ordered half: [head][row r][c0][t] with t = nf*2+jj
        int h = i >> 14, rem = i & 16383;
        int r = rem >> 7, q = rem & 127;
        int c0 = q >> 5, t = q & 31;
        int nf = t >> 1, jj = t & 1;
        int m = nf*8 + c0*2 + jj;      // attended column
        int t1 = r >> 6, h1 = (r >> 3) & 7, w1i = r & 7;
        int t2 = m >> 6, h2 = (m >> 3) & 7, w2i = m & 7;
        int bi = (t1 - t2 + 1)*225 + (h1 - h2 + 7)*15 + (w1i - w2i + 7);
        bf[i] = __float2half_rn(bt[bi*HEADS + h]);
    }
}

// ---------------- templated fp16 mma GEMM (3-stage cp.async) ---------------
// modes: 0 plain->half (Q channels pre-scaled)  1 GELU->half  2 +resid->f32
//        3 +win-reverse +resid->f32 AND fused LN2 -> half xw (BN_=192 only)
#define BM 128
#define BK 64
#define PADH 72

template<int BN_, int WMG, int MF, int MINB>
__global__ __launch_bounds__(256, MINB)
void gemm_t(const __half* __restrict__ A, const __half* __restrict__ W,
            const float* __restrict__ bias, void* __restrict__ outv,
            int N, int K, int mode, const float* __restrict__ resid,
            const float* __restrict__ g2, const float* __restrict__ b2,
            __half* __restrict__ xw_out)
{
    constexpr int NF = 6;
    constexpr int STG_HALVES = (BM + BN_) * PADH;
    extern __shared__ __half smh[];
    __half* stg[3] = { smh, smh + STG_HALVES, smh + 2*STG_HALVES };

    int tid = threadIdx.x;
    int lane = tid & 31, wid = tid >> 5;
    int warp_m = wid % WMG, warp_n = wid / WMG;
    int col0 = blockIdx.x * BN_;
    int row0 = blockIdx.y * BM;
    int NC = K / BK;

    float acc[MF][NF][4];
    #pragma unroll
    for (int i = 0; i < MF; ++i)
        #pragma unroll
        for (int j = 0; j < NF; ++j)
            #pragma unroll
            for (int k = 0; k < 4; ++k) acc[i][j][k] = 0.f;

    int r0 = lane >> 2, c0 = lane & 3;

    int arow  = (lane & 7) + 8*((lane >> 3) & 1);
    int akoff = (lane >> 4) * 8;
    uint32_t aoff[MF];
    #pragma unroll
    for (int mf = 0; mf < MF; ++mf)
        aoff[mf] = (uint32_t)(((warp_m*(MF*16) + mf*16 + arow)*PADH + akoff) * 2);
    int bmat   = lane >> 3;
    int brow   = lane & 7;
    int bnhalf = bmat >> 1;
    int bkoff  = (bmat & 1) * 8;
    uint32_t boff[3];
    #pragma unroll
    for (int j = 0; j < 3; ++j)
        boff[j] = (uint32_t)(BM*PADH*2 +
                  ((warp_n*48 + (2*j + bnhalf)*8 + brow)*PADH + bkoff) * 2);

    auto load_tiles = [&](int kt, __half* stage) {
        uint32_t aA = smem_u32(stage), aB = smem_u32(stage + BM*PADH);
        #pragma unroll
        for (int j = 0; j < 4; ++j) {
            int idx = tid + j*256;
            int r = idx >> 3, c8 = idx & 7;
            cp_async16(aA + (uint32_t)(r*PADH + c8*8)*2, A + (size_t)(row0 + r)*K + kt + c8*8);
        }
        #pragma unroll
        for (int j = 0; j < BN_/32; ++j) {
            int idx = tid + j*256;
            int r = idx >> 3, c8 = idx & 7;
            cp_async16(aB + (uint32_t)(r*PADH + c8*8)*2, W + (size_t)(col0 + r)*K + kt + c8*8);
        }
    };

    load_tiles(0,  stg[0]); cp_commit();
    load_tiles(BK, stg[1]); cp_commit();

    for (int i = 0; i < NC; ++i) {
        cp_wait1();
        __syncthreads();
        if (i + 2 < NC)
            load_tiles((i+2)*BK, stg[(i+2)%3]);
        cp_commit();

        uint32_t base = smem_u32(stg[i % 3]);

        #pragma unroll
        for (int kk = 0; kk < 4; ++kk) {
            uint32_t kb = kk*16*2;
            uint32_t af[MF][4], bf[NF][2];
            #pragma unroll
            for (int mf = 0; mf < MF; ++mf)
                ldsm_x4(af[mf], base + aoff[mf] + kb);
            #pragma unroll
            for (int j = 0; j < 3; ++j) {
                uint32_t br[4];
                ldsm_x4(br, base + boff[j] + kb);
                bf[2*j  ][0] = br[0]; bf[2*j  ][1] = br[1];
                bf[2*j+1][0] = br[2]; bf[2*j+1][1] = br[3];
            }
            #pragma unroll
            for (int mf = 0; mf < MF; ++mf)
                #pragma unroll
                for (int nf = 0; nf < NF; ++nf)
                    mma_f16(acc[mf][nf], af[mf], bf[nf]);
        }
    }

    if (mode != 3) {
        #pragma unroll
        for (int mf = 0; mf < MF; ++mf) {
            #pragma unroll
            for (int half = 0; half < 2; ++half) {
                int gm = row0 + warp_m*(MF*16) + mf*16 + half*8 + r0;
                size_t rowbase = (size_t)gm * N;
                #pragma unroll
                for (int nf = 0; nf < NF; ++nf) {
                    int gn = col0 + warp_n*48 + nf*8 + c0*2;
                    float v0 = acc[mf][nf][half*2 + 0] + bias[gn];
                    float v1 = acc[mf][nf][half*2 + 1] + bias[gn + 1];
                    if (mode == 0) {
                        if (gn < CC) { v0 *= ATTSCALE; v1 *= ATTSCALE; }   // pre-scale Q
                        *(__half2*)((__half*)outv + rowbase + gn) = __floats2half2_rn(v0, v1);
                    } else if (mode == 1) {
                        *(__half2*)((__half*)outv + rowbase + gn) =
                            __floats2half2_rn(gelu_exact(v0), gelu_exact(v1));
                    } else {
                        const float2 rr = *(const float2*)(resid + rowbase + gn);
                        float2 o; o.x = v0 + rr.x; o.y = v1 + rr.y;
                        *(float2*)((float*)outv + rowbase + gn) = o;
                    }
                }
            }
        }
        return;
    }

    // ---- mode 3: x2 = proj + bias + shortcut, fused LN2 -> xw ----
    __syncthreads();
    float* redsum = (float*)smh;
    float* redsq  = (float*)smh + 128;
    if (tid < 128) { redsum[tid] = 0.f; redsq[tid] = 0.f; }
    __syncthreads();

    int toks[MF][2];
    #pragma unroll
    for (int mf = 0; mf < MF; ++mf) {
        #pragma unroll
        for (int half = 0; half < 2; ++half) {
            int gm = row0 + warp_m*(MF*16) + mf*16 + half*8 + r0;
            int win = gm >> 7, n = gm & 127;
            int bb = win >> 10, rem = win & 1023;
            int t = (rem >> 8)*2 + (n >> 6);
            int h = ((rem >> 4) & 15)*8 + ((n >> 3) & 7);
            int w = (rem & 15)*8 + (n & 7);
            int token = ((bb*TT + t)*HH + h)*WWD + w;
            toks[mf][half] = token;
            size_t rowbase = (size_t)token * CC;

            float psum = 0.f, psq = 0.f;
            #pragma unroll
            for (int nf = 0; nf < NF; ++nf) {
                int gn = col0 + warp_n*48 + nf*8 + c0*2;
                const float2 rr = *(const float2*)(resid + rowbase + gn);
                float v0 = acc[mf][nf][half*2+0] + bias[gn]   + rr.x;
                float v1 = acc[mf][nf][half*2+1] + bias[gn+1] + rr.y;
                acc[mf][nf][half*2+0] = v0;
                acc[mf][nf][half*2+1] = v1;
                float2 o; o.x = v0; o.y = v1;
                *(float2*)((float*)outv + rowbase + gn) = o;
                psum += v0 + v1;
                psq  += v0*v0 + v1*v1;
            }
            psum += __shfl_xor_sync(0xffffffffu, psum, 1);
            psum += __shfl_xor_sync(0xffffffffu, psum, 2);
            psq  += __shfl_xor_sync(0xffffffffu, psq, 1);
            psq  += __shfl_xor_sync(0xffffffffu, psq, 2);
            if (c0 == 0) {
                int lr = warp_m*(MF*16) + mf*16 + half*8 + r0;
                atomicAdd(&redsum[lr], psum);
                atomicAdd(&redsq[lr],  psq);
            }
        }
    }
    __syncthreads();

    #pragma unroll
    for (int mf = 0; mf < MF; ++mf) {
        #pragma unroll
        for (int half = 0; half < 2; ++half) {
            int lr = warp_m*(MF*16) + mf*16 + half*8 + r0;
            float mu  = redsum[lr] * (1.0f/192.0f);
            float var = redsq[lr] * (1.0f/192.0f) - mu*mu;
            float rinv = rsqrtf(var + 1e-5f);
            size_t rowbase = (size_t)toks[mf][half] * CC;
            #pragma unroll
            for (int nf = 0; nf < NF; ++nf) {
                int gn = col0 + warp_n*48 + nf*8 + c0*2;
                float n0 = (acc[mf][nf][half*2+0] - mu)*rinv*g2[gn]   + b2[gn];
                float n1 = (acc[mf][nf][half*2+1] - mu)*rinv*g2[gn+1] + b2[gn+1];
                *(__half2*)(xw_out + rowbase + gn) = __floats2half2_rn(n0, n1);
            }
        }
    }
}

#define GSMEM192 (3*(BM+192)*PADH*2)
#define GSMEM96  (3*(BM+96)*PADH*2)

// ---------------- attention (cp.async Q/K staging) ---------------------------
#define PQH 40
#define PPH 136
#define ATT_SMEM ((128*PPH + 32*PPH)*2)     // 43520 bytes

__global__ __launch_bounds__(256, 2)
void attn_mma(const __half* __restrict__ qkv,
              const __half* __restrict__ biasf,
              __half* __restrict__ outp)
{
    extern __shared__ __half sh[];
    __half* Vts = sh + 128*PPH;

    int head = blockIdx.x, win = blockIdx.y;
    int tid = threadIdx.x, lane = tid & 31, w = tid >> 5;
    int r0 = lane >> 2, c0 = lane & 3;
    uint32_t base = smem_u32(sh);

    // ---- stage: threads 0-127 cp.async Q,K rows; threads 128-255 build V^T ----
    if (tid < 128) {
        const __half* rb = qkv + (size_t)win*NWTOK*QKVDIM + (size_t)tid*QKVDIM + head*HDIM;
        uint32_t qdst = base + (uint32_t)(tid*PQH)*2;
        uint32_t kdst = base + (uint32_t)((128 + tid)*PQH)*2;
        #pragma unroll
        for (int q = 0; q < 4; ++q) {
            cp_async16(qdst + q*16, rb + q*8);
            cp_async16(kdst + q*16, rb + CC + q*8);
        }
        cp_commit();
        cp_wait0();
    } else {
        int tok = tid - 128;
        const uint4* v4 = (const uint4*)(qkv + (size_t)win*NWTOK*QKVDIM +
                                         (size_t)tok*QKVDIM + 2*CC + head*HDIM);
        #pragma unroll
        for (int q = 0; q < 4; ++q) {
            uint4 vv = v4[q];
            const __half* vh = (const __half*)&vv;
            #pragma unroll
            for (int d = 0; d < 8; ++d) Vts[(q*8 + d)*PPH + tok] = vh[d];
        }
    }
    __syncthreads();

    int arow  = (lane & 7) + 8*((lane >> 3) & 1);
    int akoff = (lane >> 4) * 8;
    int bmat  = lane >> 3, brow = lane & 7;
    int bnhalf = bmat >> 1, bkoff = (bmat & 1) * 8;

    float s[16][4];
    #pragma unroll
    for (int b = 0; b < 16; ++b)
        #pragma unroll
        for (int c = 0; c < 4; ++c) s[b][c] = 0.f;

    {
        uint32_t aoffQ = (uint32_t)(((w*16 + arow)*PQH + akoff) * 2);
        #pragma unroll
        for (int kk = 0; kk < 2; ++kk) {
            uint32_t kb = kk*32;
            uint32_t af[4];
            ldsm_x4(af, base + aoffQ + kb);
            #pragma unroll
            for (int j = 0; j < 8; ++j) {
                uint32_t br[4];
                uint32_t bo = (uint32_t)(128*PQH*2 +
                              (((2*j + bnhalf)*8 + brow)*PQH + bkoff) * 2);
                ldsm_x4(br, base + bo + kb);
                uint32_t b0[2] = { br[0], br[1] };
                uint32_t b1[2] = { br[2], br[3] };
                mma_f16(s[2*j  ], af, b0);
                mma_f16(s[2*j+1], af, b1);
            }
        }
    }

    // ---- half fragment-ordered bias + row softmax (Q pre-scaled) ----
    float inv[2];
    #pragma unroll
    for (int half = 0; half < 2; ++half) {
        int r = w*16 + half*8 + r0;
        const uint4* bp = (const uint4*)(biasf +
                           (((size_t)head*128 + r)*4 + c0)*32);
        float mx = -1e30f;
        #pragma unroll
        for (int q = 0; q < 4; ++q) {
            uint4 raw = bp[q];
            const __half2* hp = (const __half2*)&raw;
            #pragma unroll
            for (int p = 0; p < 4; ++p) {
                int nf = q*4 + p;
                float2 bb = __half22float2(hp[p]);
                float v0 = s[nf][half*2+0] + bb.x;
                float v1 = s[nf][half*2+1] + bb.y;
                s[nf][half*2+0] = v0;
                s[nf][half*2+1] = v1;
                mx = fmaxf(mx, fmaxf(v0, v1));
            }
        }
        mx = fmaxf(mx, __shfl_xor_sync(0xffffffffu, mx, 1));
        mx = fmaxf(mx, __shfl_xor_sync(0xffffffffu, mx, 2));
        float sum = 0.f;
        #pragma unroll
        for (int nf = 0; nf < 16; ++nf) {
            float e0 = __expf(s[nf][half*2+0] - mx);
            float e1 = __expf(s[nf][half*2+1] - mx);
            s[nf][half*2+0] = e0;
            s[nf][half*2+1] = e1;
            sum += e0 + e1;
        }
        sum += __shfl_xor_sync(0xffffffffu, sum, 1);
        sum += __shfl_xor_sync(0xffffffffu, sum, 2);
        inv[half] = 1.0f / sum;
    }

    __syncthreads();   // all warps done reading Qs/Ks before P overwrites

    // ---- store P via stmatrix ----
    #pragma unroll
    for (int half = 0; half < 2; ++half) {
        int srow = w*16 + half*8 + (lane & 7);
        int mtx  = lane >> 3;
        #pragma unroll
        for (int t = 0; t < 4; ++t) {
            uint32_t addr = base + (uint32_t)((srow*PPH + (4*mtx + t)*8) * 2);
            stsm_x4(addr,
                    pack2(s[t    ][half*2+0], s[t    ][half*2+1]),
                    pack2(s[4+t  ][half*2+0], s[4+t  ][half*2+1]),
                    pack2(s[8+t  ][half*2+0], s[8+t  ][half*2+1]),
                    pack2(s[12+t ][half*2+0], s[12+t ][half*2+1]));
        }
    }
    __syncthreads();

    float o[4][4];
    #pragma unroll
    for (int b = 0; b < 4; ++b)
        #pragma unroll
        for (int c = 0; c < 4; ++c) o[b][c] = 0.f;

    {
        uint32_t aoffP = (uint32_t)(((w*16 + arow)*PPH + akoff) * 2);
        #pragma unroll
        for (int kk = 0; kk < 8; ++kk) {
            uint32_t kb = kk*32;
            uint32_t af[4];
            ldsm_x4(af, base + aoffP + kb);
            #pragma unroll
            for (int j = 0; j < 2; ++j) {
                uint32_t br[4];
                uint32_t bo = (uint32_t)(128*PPH*2 +
                              (((2*j + bnhalf)*8 + brow)*PPH + bkoff) * 2);
                ldsm_x4(br, base + bo + kb);
                uint32_t b0[2] = { br[0], br[1] };
                uint32_t b1[2] = { br[2], br[3] };
                mma_f16(o[2*j  ], af, b0);
                mma_f16(o[2*j+1], af, b1);
            }
        }
    }

    #pragma unroll
    for (int half = 0; half < 2; ++half) {
        int r = w*16 + half*8 + r0;
        float sc = inv[half];
        __half* op = outp + ((size_t)win*NWTOK + r)*CC + head*HDIM;
        #pragma unroll
        for (int nf = 0; nf < 4; ++nf)
            *(__half2*)(op + nf*8 + 2*c0) =
                __floats2half2_rn(o[nf][half*2+0]*sc, o[nf][half*2+1]*sc);
    }
}

// ---------------- launch ----------------
extern "C" void kernel_launch(void* const* d_in, const int* in_sizes, int n_in,
                              void* d_out, int out_size)
{
    const float* x        = (const float*)d_in[0];
    const float* norm1_g  = (const float*)d_in[1];
    const float* norm1_b  = (const float*)d_in[2];
    const float* qkv_w    = (const float*)d_in[3];
    const float* qkv_b    = (const float*)d_in[4];
    const float* bias_tab = (const float*)d_in[5];
    const float* proj_w   = (const float*)d_in[6];
    const float* proj_b   = (const float*)d_in[7];
    const float* norm2_g  = (const float*)d_in[8];
    const float* norm2_b  = (const float*)d_in[9];
    const float* fc1_w    = (const float*)d_in[10];
    const float* fc1_b    = (const float*)d_in[11];
    const float* fc2_w    = (const float*)d_in[12];
    const float* fc2_b    = (const float*)d_in[13];
    float* out = (float*)d_out;

    __half *xw, *qkvb, *attno, *h1, *wq, *wp, *w1, *w2, *bf;
    float *x2;
    cudaGetSymbolAddress((void**)&xw,    g_xw);
    cudaGetSymbolAddress((void**)&qkvb,  g_qkv);
    cudaGetSymbolAddress((void**)&attno, g_attnout);
    cudaGetSymbolAddress((void**)&x2,    g_x2);
    cudaGetSymbolAddress((void**)&h1,    g_h1);
    cudaGetSymbolAddress((void**)&wq,    g_wq);
    cudaGetSymbolAddress((void**)&wp,    g_wp);
    cudaGetSymbolAddress((void**)&w1,    g_w1);
    cudaGetSymbolAddress((void**)&w2,    g_w2);
    cudaGetSymbolAddress((void**)&bf,    g_biasf);

    cudaFuncSetAttribute(attn_mma, cudaFuncAttributeMaxDynamicSharedMemorySize, ATT_SMEM);
    cudaFuncSetAttribute(gemm_t<192,2,4,1>, cudaFuncAttributeMaxDynamicSharedMemorySize, GSMEM192);
    cudaFuncSetAttribute(gemm_t<96,4,2,2>,  cudaFuncAttributeMaxDynamicSharedMemorySize, GSMEM96);

    // merged setup
    setup_kernel<<<(NSETUP+255)/256, 256>>>(qkv_w, proj_w, fc1_w, fc2_w, bias_tab,
                                            wq, wp, w1, w2, bf);

    // 1. LN1 + window partition -> half
    ln_kernel<<<TOKENS/8, 256>>>(x, norm1_g, norm1_b, xw, 1);
    // 2. QKV GEMM -> half (Q channels pre-scaled by ATTSCALE)
    gemm_t<96,4,2,2><<<dim3(QKVDIM/96, TOKENS/BM), 256, GSMEM96>>>(xw, wq, qkv_b, qkvb,
        QKVDIM, CC, 0, nullptr, nullptr, nullptr, nullptr);
    // 3. windowed attention -> half
    attn_mma<<<dim3(HEADS, NWIN), 256, ATT_SMEM>>>(qkvb, bf, attno);
    // 4. proj + window-reverse + residual -> x2 (f32), fused LN2 -> xw (half)
    gemm_t<192,2,4,1><<<dim3(CC/192, TOKENS/BM), 256, GSMEM192>>>(attno, wp, proj_b, x2,
        CC, CC, 3, x, norm2_g, norm2_b, xw);
    // 5. FC1 + GELU -> half
    gemm_t<96,4,2,2><<<dim3(HIDDEN/96, TOKENS/BM), 256, GSMEM96>>>(xw, w1, fc1_b, h1,
        HIDDEN, CC, 1, nullptr, nullptr, nullptr, nullptr);
    // 6. FC2 + residual -> out (f32)
    gemm_t<96,4,2,2><<<dim3(CC/96, TOKENS/BM), 256, GSMEM96>>>(h1, w2, fc2_b, out,
        CC, HIDDEN, 2, x2, nullptr, nullptr, nullptr);
}